// round 15
// baseline (speedup 1.0000x reference)
#include <cuda_runtime.h>
#include <cuda_fp16.h>
#include <cstdint>
#include <math.h>

// Problem constants
#define BATCH   2
#define SEQ     2048
#define DMODEL  1024
#define NHEAD   16
#define DKH     64
#define DFF     4096
#define NROWS   (BATCH * SEQ)   // 4096
#define NQKV    3072            // fused QKV output width
// 1/sqrt(64) * log2(e): folded into Wq/bq at prep time (scores in log2 domain)
#define SCL 0.1803368801111244f

// ===========================================================================
// Helpers
// ===========================================================================
__device__ __forceinline__ uint32_t smem_to_u32(const void* p) {
    uint32_t a;
    asm("{ .reg .u64 t; cvta.to.shared.u64 t, %1; cvt.u32.u64 %0, t; }" : "=r"(a) : "l"(p));
    return a;
}
__device__ __forceinline__ void cp_async16(uint32_t s, const void* g) {
    asm volatile("cp.async.cg.shared.global [%0], [%1], 16;" :: "r"(s), "l"(g));
}
__device__ __forceinline__ void cp_commit() {
    asm volatile("cp.async.commit_group;" ::: "memory");
}
template <int N>
__device__ __forceinline__ void cp_wait() {
    asm volatile("cp.async.wait_group %0;" :: "n"(N) : "memory");
}
__device__ __forceinline__ void ldmx4(uint32_t* r, uint32_t addr) {
    asm volatile("ldmatrix.sync.aligned.m8n8.x4.shared.b16 {%0,%1,%2,%3}, [%4];"
                 : "=r"(r[0]), "=r"(r[1]), "=r"(r[2]), "=r"(r[3]) : "r"(addr));
}
__device__ __forceinline__ void ldmx4t(uint32_t* r, uint32_t addr) {
    asm volatile("ldmatrix.sync.aligned.m8n8.x4.trans.shared.b16 {%0,%1,%2,%3}, [%4];"
                 : "=r"(r[0]), "=r"(r[1]), "=r"(r[2]), "=r"(r[3]) : "r"(addr));
}
__device__ __forceinline__ void mma16816(float* d, const uint32_t* a, const uint32_t* b) {
    asm volatile("mma.sync.aligned.m16n8k16.row.col.f32.f16.f16.f32 "
                 "{%0,%1,%2,%3}, {%4,%5,%6,%7}, {%8,%9}, {%0,%1,%2,%3};"
                 : "+f"(d[0]), "+f"(d[1]), "+f"(d[2]), "+f"(d[3])
                 : "r"(a[0]), "r"(a[1]), "r"(a[2]), "r"(a[3]), "r"(b[0]), "r"(b[1]));
}
__device__ __forceinline__ uint32_t pack2h(float a, float b) {
    __half2 h = __floats2half2_rn(a, b);
    return *reinterpret_cast<uint32_t*>(&h);
}

// ===========================================================================
// Scratch (__device__ globals; no cudaMalloc allowed)
// ===========================================================================
__device__ __half g_xn [NROWS * DMODEL];
__device__ __half g_at [NROWS * DMODEL];
__device__ __half g_ff [NROWS * DFF];
__device__ __half g_qkv[NROWS * NQKV];
// fp16 weights in ORIGINAL [K,N] layout: [Wq | Wk | Wv | Wo | W1 | W2]
#define WOFF_O  (3145728u)
#define WOFF_W1 (4194304u)
#define WOFF_W2 (8388608u)
__device__ __half g_w[12582912];
__device__ float g_bqkv[NQKV];
__device__ float g_h[NROWS * DMODEL];

// ===========================================================================
// Prep: convert all 6 weights fp32 -> fp16 (layout preserved) + bias concat.
// Wq segment and bq are pre-scaled by SCL (softmax scale folded into Q).
// ===========================================================================
__global__ __launch_bounds__(256) void prep_kernel(
    const float* __restrict__ Wq, const float* __restrict__ Wk,
    const float* __restrict__ Wv, const float* __restrict__ Wo,
    const float* __restrict__ W1, const float* __restrict__ W2,
    const float* __restrict__ bq, const float* __restrict__ bk,
    const float* __restrict__ bv, __half* __restrict__ w,
    float* __restrict__ bqkv)
{
    int t = blockIdx.x * 256 + threadIdx.x;
    if (t < NQKV)
        bqkv[t] = (t < 1024) ? bq[t] * SCL
                : (t < 2048) ? bk[t - 1024] : bv[t - 2048];

    size_t i = (size_t)t * 8;
    const float* s; size_t o;
    float scale = 1.0f;
    if (i < 4194304) {
        int sel = (int)(i >> 20);
        s = (sel == 0) ? Wq : (sel == 1) ? Wk : (sel == 2) ? Wv : Wo;
        if (sel == 0) scale = SCL;
        o = i & 1048575u;
    } else if (i < 8388608) { s = W1; o = i - 4194304; }
    else                    { s = W2; o = i - 8388608; }
    float4 v0 = *(const float4*)(s + o);
    float4 v1 = *(const float4*)(s + o + 4);
    uint4 p;
    p.x = pack2h(v0.x * scale, v0.y * scale);
    p.y = pack2h(v0.z * scale, v0.w * scale);
    p.z = pack2h(v1.x * scale, v1.y * scale);
    p.w = pack2h(v1.z * scale, v1.w * scale);
    *(uint4*)(w + i) = p;
}

// ===========================================================================
// LayerNorm (fp16 output)
// ===========================================================================
__global__ __launch_bounds__(256) void ln_kernel(
    const float* __restrict__ X, const float* __restrict__ gamma,
    const float* __restrict__ beta, __half* __restrict__ Y)
{
    int row = blockIdx.x;
    int t   = threadIdx.x;
    float4 xv = ((const float4*)(X + (size_t)row * DMODEL))[t];
    float s = xv.x + xv.y + xv.z + xv.w;
    float q = xv.x * xv.x + xv.y * xv.y + xv.z * xv.z + xv.w * xv.w;
#pragma unroll
    for (int off = 16; off > 0; off >>= 1) {
        s += __shfl_xor_sync(0xffffffffu, s, off);
        q += __shfl_xor_sync(0xffffffffu, q, off);
    }
    __shared__ float ss[8], sq[8];
    if ((t & 31) == 0) { ss[t >> 5] = s; sq[t >> 5] = q; }
    __syncthreads();
    __shared__ float smu, srstd;
    if (t == 0) {
        float S = 0.f, Q = 0.f;
#pragma unroll
        for (int i = 0; i < 8; i++) { S += ss[i]; Q += sq[i]; }
        float mu  = S * (1.0f / DMODEL);
        float var = Q * (1.0f / DMODEL) - mu * mu;
        smu = mu; srstd = rsqrtf(var + 1e-5f);
    }
    __syncthreads();
    float mu = smu, r = srstd;
    float4 g4 = ((const float4*)gamma)[t];
    float4 b4 = ((const float4*)beta)[t];
    uint32_t p0 = pack2h((xv.x - mu) * r * g4.x + b4.x, (xv.y - mu) * r * g4.y + b4.y);
    uint32_t p1 = pack2h((xv.z - mu) * r * g4.z + b4.z, (xv.w - mu) * r * g4.w + b4.w);
    size_t base = (size_t)row * DMODEL + t * 4;
    *(uint32_t*)(Y + base)     = p0;
    *(uint32_t*)(Y + base + 2) = p1;
}

// ===========================================================================
// HMMA fp16 GEMM (champion config, UNCHANGED): C = A @ W + bias.
// CTA tile 128x128, 4 warps (2M x 2N), warp tile 64x64, 128 threads.
// K chunk 64, 3-stage cp.async pipeline, 2 CTAs/SM.
// modes: 0 fp32+bias | 1 fp32+bias+res | 2 fp16+bias+relu | 3 fp16+bias
// ===========================================================================
#define BKC 64
#define ASTRIDE 144
#define BSTRIDE 272
#define ATILE (128 * ASTRIDE)
#define BTILE (64 * BSTRIDE)
#define STG (ATILE + BTILE)
#define NSTAGE 3
#define GSMEM (NSTAGE * STG)

__device__ __forceinline__ void load_stage(
    const __half* __restrict__ A, const __half* __restrict__ Bp,
    int m0, int k0, int K, int bN, uint32_t sbase)
{
    int tid = threadIdx.x;
#pragma unroll
    for (int j = 0; j < 8; j++) {
        int e = tid + j * 128;
        int row = e >> 3, s = e & 7;
        cp_async16(sbase + row * ASTRIDE + s * 16,
                   A + (size_t)(m0 + row) * K + k0 + s * 8);
    }
#pragma unroll
    for (int j = 0; j < 8; j++) {
        int e = tid + j * 128;
        int row = e >> 4, s = e & 15;
        cp_async16(sbase + ATILE + row * BSTRIDE + s * 16,
                   Bp + (size_t)(k0 + row) * bN + s * 8);
    }
}

__global__ __launch_bounds__(128, 2) void gemm_hmma_kernel(
    const __half* __restrict__ A, const __half* __restrict__ Bw,
    const float* __restrict__ bias, const float* __restrict__ res,
    float* __restrict__ outF, __half* __restrict__ outH,
    int N, int K, int segN, int segElems, int bN, int mode)
{
    extern __shared__ char smem[];
    uint32_t sb = smem_to_u32(smem);
    int tid = threadIdx.x, wid = tid >> 5, lane = tid & 31;
    int m0 = blockIdx.y * 128, n0 = blockIdx.x * 128;
    int wy = wid >> 1, wx = wid & 1;

    const __half* Bp = Bw + (size_t)(n0 / segN) * (size_t)segElems + (n0 % segN);

    float acc[4][8][4];
#pragma unroll
    for (int a = 0; a < 4; a++)
#pragma unroll
        for (int b = 0; b < 8; b++)
#pragma unroll
            for (int c = 0; c < 4; c++) acc[a][b][c] = 0.f;

    const int NC = K >> 6;

    load_stage(A, Bp, m0, 0, K, bN, sb);
    cp_commit();
    load_stage(A, Bp, m0, BKC, K, bN, sb + STG);
    cp_commit();

    int arow = (lane & 7) + ((lane >> 3) & 1) * 8;
    int akof = (lane >> 4) * 16;
    int vrow = (lane & 7) + ((lane >> 3) & 1) * 8;
    int vbyt = (lane >> 4) * 16;

    for (int i = 0; i < NC; i++) {
        if (i + 1 < NC) cp_wait<1>(); else cp_wait<0>();
        __syncthreads();

        uint32_t st = sb + (i % NSTAGE) * STG;
#pragma unroll
        for (int kh = 0; kh < 4; kh++) {
            uint32_t Af[4][4];
            uint32_t Bf[8][2];
#pragma unroll
            for (int mt = 0; mt < 4; mt++) {
                uint32_t addr = st + (wy * 64 + mt * 16 + arow) * ASTRIDE + kh * 32 + akof;
                ldmx4(Af[mt], addr);
            }
#pragma unroll
            for (int ntp = 0; ntp < 4; ntp++) {
                uint32_t addr = st + ATILE + (kh * 16 + vrow) * BSTRIDE +
                                (wx * 64 + ntp * 16) * 2 + vbyt;
                uint32_t r[4];
                ldmx4t(r, addr);
                Bf[ntp * 2][0] = r[0]; Bf[ntp * 2][1] = r[1];
                Bf[ntp * 2 + 1][0] = r[2]; Bf[ntp * 2 + 1][1] = r[3];
            }
#pragma unroll
            for (int mt = 0; mt < 4; mt++)
#pragma unroll
                for (int nt = 0; nt < 8; nt++)
                    mma16816(acc[mt][nt], Af[mt], Bf[nt]);
        }

        if (i + 2 < NC) {
            load_stage(A, Bp, m0, (i + 2) * BKC, K, bN, sb + ((i + 2) % NSTAGE) * STG);
            cp_commit();
        }
    }

    // Epilogue
#pragma unroll
    for (int mt = 0; mt < 4; mt++) {
#pragma unroll
        for (int nt = 0; nt < 8; nt++) {
            int r0 = m0 + wy * 64 + mt * 16 + (lane >> 2);
            int c  = n0 + wx * 64 + nt * 8 + (lane & 3) * 2;
            float b0 = bias[c], b1 = bias[c + 1];
#pragma unroll
            for (int half = 0; half < 2; half++) {
                int r = r0 + half * 8;
                float v0 = acc[mt][nt][half * 2 + 0] + b0;
                float v1 = acc[mt][nt][half * 2 + 1] + b1;
                size_t o = (size_t)r * N + c;
                if (mode >= 2) {
                    if (mode == 2) { v0 = fmaxf(v0, 0.f); v1 = fmaxf(v1, 0.f); }
                    *(uint32_t*)(outH + o) = pack2h(v0, v1);
                } else {
                    if (mode == 1) {
                        float2 rr = *(const float2*)(res + o);
                        v0 += rr.x; v1 += rr.y;
                    }
                    float2 w; w.x = v0; w.y = v1;
                    *(float2*)(outF + o) = w;
                }
            }
        }
    }
}

// ===========================================================================
// HMMA fp16 flash attention (causal), exp2-domain softmax, pre-scaled Q.
// Block: 256 threads (8 warps), 128 q-rows (16/warp), KV tiles of 64.
// 3-stage KV pipeline, ONE __syncthreads per tile (GEMM-style ordering).
// Diagonal tiles skip fully-masked 16-key groups (gmax, warp-uniform).
// ===========================================================================
#define AQ 128
#define ATK 64
#define ASTR 144
#define A_Q 0
#define A_ST (128 * ASTR)
#define A_STG (2 * 64 * ASTR)
#define A_V (64 * ASTR)
#define ATT_SMEM (A_ST + 3 * A_STG)   // 73728

__device__ __forceinline__ void load_kv_tile(
    const __half* __restrict__ kp, const __half* __restrict__ vp,
    size_t gbase, int k0, uint32_t sbase)
{
    int tid = threadIdx.x;
#pragma unroll
    for (int j = 0; j < 2; j++) {
        int e = tid + j * 256;
        int row = e >> 3, ch = e & 7;
        size_t g = gbase + (size_t)(k0 + row) * NQKV + ch * 8;
        uint32_t so = row * ASTR + ch * 16;
        cp_async16(sbase + so,       kp + g);
        cp_async16(sbase + A_V + so, vp + g);
    }
}

__global__ __launch_bounds__(256, 2) void flash_hmma_kernel(
    const __half* __restrict__ qkv, __half* __restrict__ O)
{
    extern __shared__ char smem[];
    uint32_t sb = smem_to_u32(smem);
    int tid = threadIdx.x, wid = tid >> 5, lane = tid & 31;
    int bh = blockIdx.y, b = bh >> 4, h = bh & 15;
    int q0 = (gridDim.x - 1 - blockIdx.x) * AQ;   // heavy tiles first
    size_t gbase = (size_t)(b * SEQ) * NQKV + h * DKH;

    const __half* qp = qkv;
    const __half* kp = qkv + DMODEL;
    const __half* vp = qkv + 2 * DMODEL;

    // Prologue: group0 = Q + KV tile 0, group1 = KV tile 1 (ntiles >= 2 always)
#pragma unroll
    for (int j = 0; j < 4; j++) {
        int e = tid + j * 256;
        int row = e >> 3, ch = e & 7;
        size_t g = gbase + (size_t)(q0 + row) * NQKV + ch * 8;
        cp_async16(sb + A_Q + row * ASTR + ch * 16, qp + g);
    }
    load_kv_tile(kp, vp, gbase, 0, sb + A_ST);
    cp_commit();
    load_kv_tile(kp, vp, gbase, ATK, sb + A_ST + A_STG);
    cp_commit();

    const int ntiles = q0 / ATK + 2;

    float Sv[32], Oa[32];
#pragma unroll
    for (int i = 0; i < 32; i++) Oa[i] = 0.f;
    float m0 = -1e30f, m1 = -1e30f, l0 = 0.f, l1 = 0.f;

    int arow = (lane & 7) + ((lane >> 3) & 1) * 8;
    int akof = (lane >> 4) * 16;
    int brow = (lane & 7) + (lane >> 4) * 8;
    int bkof = ((lane >> 3) & 1) * 16;
    int vrow = (lane & 7) + ((lane >> 3) & 1) * 8;
    int vbyt = (lane >> 4) * 16;

    int wq = q0 + (wid << 4);
    int qrow0 = wq + (lane >> 2);

    for (int jt = 0; jt < ntiles; jt++) {
        if (jt + 1 < ntiles) cp_wait<1>(); else cp_wait<0>();
        __syncthreads();

        int k0 = jt * ATK;
        if (k0 <= wq + 15) {
            uint32_t stk = sb + A_ST + (jt % 3) * A_STG;
            int gmax = ((wq + 15 - k0) >> 4) + 1;
            if (gmax > 4) gmax = 4;
#pragma unroll
            for (int i = 0; i < 32; i++) Sv[i] = 0.f;
            // --- scores: Q x K^T (log2 domain), dead key-groups skipped ---
#pragma unroll
            for (int ks = 0; ks < 4; ks++) {
                uint32_t qf[4];
                uint32_t qaddr = sb + A_Q + (wid * 16 + arow) * ASTR + ks * 32 + akof;
                ldmx4(qf, qaddr);
#pragma unroll
                for (int g = 0; g < 4; g++) {
                    if (g < gmax) {
                        uint32_t kf[4];
                        uint32_t kaddr = stk + (g * 16 + brow) * ASTR + ks * 32 + bkof;
                        ldmx4(kf, kaddr);
                        mma16816(&Sv[(g * 2) * 4],     qf, &kf[0]);
                        mma16816(&Sv[(g * 2 + 1) * 4], qf, &kf[2]);
                    }
                }
            }
            // --- tile max (interior fast path vs diagonal mask) ---
            float mt0 = -1e30f, mt1 = -1e30f;
            if (k0 + ATK - 1 <= wq) {
#pragma unroll
                for (int j = 0; j < 8; j++) {
                    mt0 = fmaxf(mt0, fmaxf(Sv[j * 4 + 0], Sv[j * 4 + 1]));
                    mt1 = fmaxf(mt1, fmaxf(Sv[j * 4 + 2], Sv[j * 4 + 3]));
                }
            } else {
                int keyb = k0 + ((lane & 3) << 1);
#pragma unroll
                for (int j = 0; j < 8; j++) {
                    if (j < 2 * gmax) {
                        int key = keyb + j * 8;
                        float s0 = Sv[j * 4 + 0]; if (key     > qrow0)     s0 = -1e30f;
                        float s1 = Sv[j * 4 + 1]; if (key + 1 > qrow0)     s1 = -1e30f;
                        float s2 = Sv[j * 4 + 2]; if (key     > qrow0 + 8) s2 = -1e30f;
                        float s3 = Sv[j * 4 + 3]; if (key + 1 > qrow0 + 8) s3 = -1e30f;
                        Sv[j * 4 + 0] = s0; Sv[j * 4 + 1] = s1;
                        Sv[j * 4 + 2] = s2; Sv[j * 4 + 3] = s3;
                        mt0 = fmaxf(mt0, fmaxf(s0, s1));
                        mt1 = fmaxf(mt1, fmaxf(s2, s3));
                    }
                }
            }
            mt0 = fmaxf(mt0, __shfl_xor_sync(0xffffffffu, mt0, 1));
            mt0 = fmaxf(mt0, __shfl_xor_sync(0xffffffffu, mt0, 2));
            mt1 = fmaxf(mt1, __shfl_xor_sync(0xffffffffu, mt1, 1));
            mt1 = fmaxf(mt1, __shfl_xor_sync(0xffffffffu, mt1, 2));
            float mn0 = fmaxf(m0, mt0), mn1 = fmaxf(m1, mt1);
            float c0 = exp2f(m0 - mn0), c1 = exp2f(m1 - mn1);
            l0 *= c0; l1 *= c1;
#pragma unroll
            for (int j = 0; j < 8; j++) {
                Oa[j * 4 + 0] *= c0; Oa[j * 4 + 1] *= c0;
                Oa[j * 4 + 2] *= c1; Oa[j * 4 + 3] *= c1;
            }
            float sum0 = 0.f, sum1 = 0.f;
#pragma unroll
            for (int j = 0; j < 8; j++) {
                if (j < 2 * gmax) {
                    float p0 = exp2f(Sv[j * 4 + 0] - mn0);
                    float p1 = exp2f(Sv[j * 4 + 1] - mn0);
                    float p2 = exp2f(Sv[j * 4 + 2] - mn1);
                    float p3 = exp2f(Sv[j * 4 + 3] - mn1);
                    Sv[j * 4 + 0] = p0; Sv[j * 4 + 1] = p1;
                    Sv[j * 4 + 2] = p2; Sv[j * 4 + 3] = p3;
                    sum0 += p0 + p1; sum1 += p2 + p3;
                }
            }
            sum0 += __shfl_xor_sync(0xffffffffu, sum0, 1);
            sum0 += __shfl_xor_sync(0xffffffffu, sum0, 2);
            sum1 += __shfl_xor_sync(0xffffffffu, sum1, 1);
            sum1 += __shfl_xor_sync(0xffffffffu, sum1, 2);
            l0 += sum0; l1 += sum1;
            m0 = mn0; m1 = mn1;
            // --- P x V, dead key-groups skipped ---
#pragma unroll
            for (int ks = 0; ks < 4; ks++) {
                if (ks < gmax) {
                    uint32_t pf[4];
                    pf[0] = pack2h(Sv[8 * ks + 0], Sv[8 * ks + 1]);
                    pf[1] = pack2h(Sv[8 * ks + 2], Sv[8 * ks + 3]);
                    pf[2] = pack2h(Sv[8 * ks + 4], Sv[8 * ks + 5]);
                    pf[3] = pack2h(Sv[8 * ks + 6], Sv[8 * ks + 7]);
#pragma unroll
                    for (int nt = 0; nt < 4; nt++) {
                        uint32_t vf[4];
                        uint32_t vaddr = stk + A_V + (ks * 16 + vrow) * ASTR + nt * 32 + vbyt;
                        ldmx4t(vf, vaddr);
                        mma16816(&Oa[(nt * 2) * 4],     pf, &vf[0]);
                        mma16816(&Oa[(nt * 2 + 1) * 4], pf, &vf[2]);
                    }
                }
            }
        }

        if (jt + 2 < ntiles) {
            load_kv_tile(kp, vp, gbase, (jt + 2) * ATK,
                         sb + A_ST + ((jt + 2) % 3) * A_STG);
            cp_commit();
        }
    }

    float inv0 = 1.f / l0, inv1 = 1.f / l1;
    size_t obase = (size_t)(b * SEQ) * DMODEL + h * DKH;
    size_t r0 = obase + (size_t)qrow0 * DMODEL;
    size_t r1 = obase + (size_t)(qrow0 + 8) * DMODEL;
#pragma unroll
    for (int nt = 0; nt < 8; nt++) {
        int col = nt * 8 + (lane & 3) * 2;
        *(uint32_t*)(O + r0 + col) = pack2h(Oa[nt * 4 + 0] * inv0, Oa[nt * 4 + 1] * inv0);
        *(uint32_t*)(O + r1 + col) = pack2h(Oa[nt * 4 + 2] * inv1, Oa[nt * 4 + 3] * inv1);
    }
}

// ===========================================================================
// Launcher
// ===========================================================================
extern "C" void kernel_launch(void* const* d_in, const int* in_sizes, int n_in,
                              void* d_out, int out_size)
{
    const float* x   = (const float*)d_in[0];
    const float* Wq  = (const float*)d_in[2];
    const float* bq  = (const float*)d_in[3];
    const float* Wk  = (const float*)d_in[4];
    const float* bk  = (const float*)d_in[5];
    const float* Wv  = (const float*)d_in[6];
    const float* bv  = (const float*)d_in[7];
    const float* Wo  = (const float*)d_in[8];
    const float* bo  = (const float*)d_in[9];
    const float* W1  = (const float*)d_in[10];
    const float* b1  = (const float*)d_in[11];
    const float* W2  = (const float*)d_in[12];
    const float* b2  = (const float*)d_in[13];
    const float* g1  = (const float*)d_in[14];
    const float* be1 = (const float*)d_in[15];
    const float* g2  = (const float*)d_in[16];
    const float* be2 = (const float*)d_in[17];
    float* out = (float*)d_out;

    __half *xn, *at, *ff, *qkv, *w;
    float *h, *bqkv;
    cudaGetSymbolAddress((void**)&xn, g_xn);
    cudaGetSymbolAddress((void**)&at, g_at);
    cudaGetSymbolAddress((void**)&ff, g_ff);
    cudaGetSymbolAddress((void**)&qkv, g_qkv);
    cudaGetSymbolAddress((void**)&w, g_w);
    cudaGetSymbolAddress((void**)&h, g_h);
    cudaGetSymbolAddress((void**)&bqkv, g_bqkv);

    cudaFuncSetAttribute(gemm_hmma_kernel,
                         cudaFuncAttributeMaxDynamicSharedMemorySize, GSMEM);
    cudaFuncSetAttribute(flash_hmma_kernel,
                         cudaFuncAttributeMaxDynamicSharedMemorySize, ATT_SMEM);

    // 1. prep: weight fp32->fp16 convert (Wq/bq pre-scaled) + bias concat
    prep_kernel<<<6144, 256>>>(Wq, Wk, Wv, Wo, W1, W2, bq, bk, bv, w, bqkv);
    // 2. LN1 -> fp16
    ln_kernel<<<NROWS, 256>>>(x, g1, be1, xn);
    // 3. Fused QKV projection -> fp16 (mode 3), 768 CTAs
    dim3 gQKV(NQKV / 128, NROWS / 128);
    gemm_hmma_kernel<<<gQKV, 128, GSMEM>>>(xn, w, bqkv, nullptr, nullptr, qkv,
                                           NQKV, DMODEL, 1024, 1 << 20, 1024, 3);
    // 4. Causal flash attention -> fp16
    dim3 gA(SEQ / AQ, BATCH * NHEAD);
    flash_hmma_kernel<<<gA, 256, ATT_SMEM>>>(qkv, at);
    // 5. Output projection + residual(x) -> h (fp32), 256 CTAs
    dim3 gO(DMODEL / 128, NROWS / 128);
    gemm_hmma_kernel<<<gO, 128, GSMEM>>>(at, w + WOFF_O, bo, x, h, nullptr,
                                         DMODEL, DMODEL, DMODEL, 0, DMODEL, 1);
    // 6. LN2 -> fp16
    ln_kernel<<<NROWS, 256>>>(h, g2, be2, xn);
    // 7. FFN1 + relu -> fp16, 1024 CTAs
    dim3 gF1(DFF / 128, NROWS / 128);
    gemm_hmma_kernel<<<gF1, 128, GSMEM>>>(xn, w + WOFF_W1, b1, nullptr, nullptr, ff,
                                          DFF, DMODEL, DFF, 0, DFF, 2);
    // 8. FFN2 + residual(h) -> out (fp32), 256 CTAs
    dim3 gF2(DMODEL / 128, NROWS / 128);
    gemm_hmma_kernel<<<gF2, 128, GSMEM>>>(ff, w + WOFF_W2, b2, h, out, nullptr,
                                          DMODEL, DFF, DMODEL, 0, DMODEL, 1);
}

// round 16
// speedup vs baseline: 1.0446x; 1.0446x over previous
#include <cuda_runtime.h>
#include <cuda_fp16.h>
#include <cstdint>
#include <math.h>

// Problem constants
#define BATCH   2
#define SEQ     2048
#define DMODEL  1024
#define NHEAD   16
#define DKH     64
#define DFF     4096
#define NROWS   (BATCH * SEQ)   // 4096
#define NQKV    3072            // fused QKV output width
// 1/sqrt(64) * log2(e): folded into Wq/bq at prep time (scores in log2 domain)
#define SCL 0.1803368801111244f

// ===========================================================================
// Helpers
// ===========================================================================
__device__ __forceinline__ uint32_t smem_to_u32(const void* p) {
    uint32_t a;
    asm("{ .reg .u64 t; cvta.to.shared.u64 t, %1; cvt.u32.u64 %0, t; }" : "=r"(a) : "l"(p));
    return a;
}
__device__ __forceinline__ void cp_async16(uint32_t s, const void* g) {
    asm volatile("cp.async.cg.shared.global [%0], [%1], 16;" :: "r"(s), "l"(g));
}
__device__ __forceinline__ void cp_commit() {
    asm volatile("cp.async.commit_group;" ::: "memory");
}
template <int N>
__device__ __forceinline__ void cp_wait() {
    asm volatile("cp.async.wait_group %0;" :: "n"(N) : "memory");
}
__device__ __forceinline__ void ldmx4(uint32_t* r, uint32_t addr) {
    asm volatile("ldmatrix.sync.aligned.m8n8.x4.shared.b16 {%0,%1,%2,%3}, [%4];"
                 : "=r"(r[0]), "=r"(r[1]), "=r"(r[2]), "=r"(r[3]) : "r"(addr));
}
__device__ __forceinline__ void ldmx4t(uint32_t* r, uint32_t addr) {
    asm volatile("ldmatrix.sync.aligned.m8n8.x4.trans.shared.b16 {%0,%1,%2,%3}, [%4];"
                 : "=r"(r[0]), "=r"(r[1]), "=r"(r[2]), "=r"(r[3]) : "r"(addr));
}
__device__ __forceinline__ void mma16816(float* d, const uint32_t* a, const uint32_t* b) {
    asm volatile("mma.sync.aligned.m16n8k16.row.col.f32.f16.f16.f32 "
                 "{%0,%1,%2,%3}, {%4,%5,%6,%7}, {%8,%9}, {%0,%1,%2,%3};"
                 : "+f"(d[0]), "+f"(d[1]), "+f"(d[2]), "+f"(d[3])
                 : "r"(a[0]), "r"(a[1]), "r"(a[2]), "r"(a[3]), "r"(b[0]), "r"(b[1]));
}
__device__ __forceinline__ uint32_t pack2h(float a, float b) {
    __half2 h = __floats2half2_rn(a, b);
    return *reinterpret_cast<uint32_t*>(&h);
}

// ===========================================================================
// Scratch (__device__ globals; no cudaMalloc allowed)
// ===========================================================================
__device__ __half g_xn [NROWS * DMODEL];
__device__ __half g_at [NROWS * DMODEL];
__device__ __half g_ff [NROWS * DFF];
__device__ __half g_qkv[NROWS * NQKV];
// fp16 weights in ORIGINAL [K,N] layout: [Wq | Wk | Wv | Wo | W1 | W2]
#define WOFF_O  (3145728u)
#define WOFF_W1 (4194304u)
#define WOFF_W2 (8388608u)
__device__ __half g_w[12582912];
__device__ float g_bqkv[NQKV];
__device__ float g_h[NROWS * DMODEL];

// ===========================================================================
// Prep: convert all 6 weights fp32 -> fp16 (layout preserved) + bias concat.
// Wq segment and bq are pre-scaled by SCL (softmax scale folded into Q).
// ===========================================================================
__global__ __launch_bounds__(256) void prep_kernel(
    const float* __restrict__ Wq, const float* __restrict__ Wk,
    const float* __restrict__ Wv, const float* __restrict__ Wo,
    const float* __restrict__ W1, const float* __restrict__ W2,
    const float* __restrict__ bq, const float* __restrict__ bk,
    const float* __restrict__ bv, __half* __restrict__ w,
    float* __restrict__ bqkv)
{
    int t = blockIdx.x * 256 + threadIdx.x;
    if (t < NQKV)
        bqkv[t] = (t < 1024) ? bq[t] * SCL
                : (t < 2048) ? bk[t - 1024] : bv[t - 2048];

    size_t i = (size_t)t * 8;
    const float* s; size_t o;
    float scale = 1.0f;
    if (i < 4194304) {
        int sel = (int)(i >> 20);
        s = (sel == 0) ? Wq : (sel == 1) ? Wk : (sel == 2) ? Wv : Wo;
        if (sel == 0) scale = SCL;
        o = i & 1048575u;
    } else if (i < 8388608) { s = W1; o = i - 4194304; }
    else                    { s = W2; o = i - 8388608; }
    float4 v0 = *(const float4*)(s + o);
    float4 v1 = *(const float4*)(s + o + 4);
    uint4 p;
    p.x = pack2h(v0.x * scale, v0.y * scale);
    p.y = pack2h(v0.z * scale, v0.w * scale);
    p.z = pack2h(v1.x * scale, v1.y * scale);
    p.w = pack2h(v1.z * scale, v1.w * scale);
    *(uint4*)(w + i) = p;
}

// ===========================================================================
// LayerNorm (fp16 output)
// ===========================================================================
__global__ __launch_bounds__(256) void ln_kernel(
    const float* __restrict__ X, const float* __restrict__ gamma,
    const float* __restrict__ beta, __half* __restrict__ Y)
{
    int row = blockIdx.x;
    int t   = threadIdx.x;
    float4 xv = ((const float4*)(X + (size_t)row * DMODEL))[t];
    float s = xv.x + xv.y + xv.z + xv.w;
    float q = xv.x * xv.x + xv.y * xv.y + xv.z * xv.z + xv.w * xv.w;
#pragma unroll
    for (int off = 16; off > 0; off >>= 1) {
        s += __shfl_xor_sync(0xffffffffu, s, off);
        q += __shfl_xor_sync(0xffffffffu, q, off);
    }
    __shared__ float ss[8], sq[8];
    if ((t & 31) == 0) { ss[t >> 5] = s; sq[t >> 5] = q; }
    __syncthreads();
    __shared__ float smu, srstd;
    if (t == 0) {
        float S = 0.f, Q = 0.f;
#pragma unroll
        for (int i = 0; i < 8; i++) { S += ss[i]; Q += sq[i]; }
        float mu  = S * (1.0f / DMODEL);
        float var = Q * (1.0f / DMODEL) - mu * mu;
        smu = mu; srstd = rsqrtf(var + 1e-5f);
    }
    __syncthreads();
    float mu = smu, r = srstd;
    float4 g4 = ((const float4*)gamma)[t];
    float4 b4 = ((const float4*)beta)[t];
    uint32_t p0 = pack2h((xv.x - mu) * r * g4.x + b4.x, (xv.y - mu) * r * g4.y + b4.y);
    uint32_t p1 = pack2h((xv.z - mu) * r * g4.z + b4.z, (xv.w - mu) * r * g4.w + b4.w);
    size_t base = (size_t)row * DMODEL + t * 4;
    *(uint32_t*)(Y + base)     = p0;
    *(uint32_t*)(Y + base + 2) = p1;
}

// ===========================================================================
// HMMA fp16 GEMM (champion config, UNCHANGED): C = A @ W + bias.
// CTA tile 128x128, 4 warps (2M x 2N), warp tile 64x64, 128 threads.
// K chunk 64, 3-stage cp.async pipeline, 2 CTAs/SM.
// modes: 0 fp32+bias | 1 fp32+bias+res | 2 fp16+bias+relu | 3 fp16+bias
// ===========================================================================
#define BKC 64
#define ASTRIDE 144
#define BSTRIDE 272
#define ATILE (128 * ASTRIDE)
#define BTILE (64 * BSTRIDE)
#define STG (ATILE + BTILE)
#define NSTAGE 3
#define GSMEM (NSTAGE * STG)

__device__ __forceinline__ void load_stage(
    const __half* __restrict__ A, const __half* __restrict__ Bp,
    int m0, int k0, int K, int bN, uint32_t sbase)
{
    int tid = threadIdx.x;
#pragma unroll
    for (int j = 0; j < 8; j++) {
        int e = tid + j * 128;
        int row = e >> 3, s = e & 7;
        cp_async16(sbase + row * ASTRIDE + s * 16,
                   A + (size_t)(m0 + row) * K + k0 + s * 8);
    }
#pragma unroll
    for (int j = 0; j < 8; j++) {
        int e = tid + j * 128;
        int row = e >> 4, s = e & 15;
        cp_async16(sbase + ATILE + row * BSTRIDE + s * 16,
                   Bp + (size_t)(k0 + row) * bN + s * 8);
    }
}

__global__ __launch_bounds__(128, 2) void gemm_hmma_kernel(
    const __half* __restrict__ A, const __half* __restrict__ Bw,
    const float* __restrict__ bias, const float* __restrict__ res,
    float* __restrict__ outF, __half* __restrict__ outH,
    int N, int K, int segN, int segElems, int bN, int mode)
{
    extern __shared__ char smem[];
    uint32_t sb = smem_to_u32(smem);
    int tid = threadIdx.x, wid = tid >> 5, lane = tid & 31;
    int m0 = blockIdx.y * 128, n0 = blockIdx.x * 128;
    int wy = wid >> 1, wx = wid & 1;

    const __half* Bp = Bw + (size_t)(n0 / segN) * (size_t)segElems + (n0 % segN);

    float acc[4][8][4];
#pragma unroll
    for (int a = 0; a < 4; a++)
#pragma unroll
        for (int b = 0; b < 8; b++)
#pragma unroll
            for (int c = 0; c < 4; c++) acc[a][b][c] = 0.f;

    const int NC = K >> 6;

    load_stage(A, Bp, m0, 0, K, bN, sb);
    cp_commit();
    load_stage(A, Bp, m0, BKC, K, bN, sb + STG);
    cp_commit();

    int arow = (lane & 7) + ((lane >> 3) & 1) * 8;
    int akof = (lane >> 4) * 16;
    int vrow = (lane & 7) + ((lane >> 3) & 1) * 8;
    int vbyt = (lane >> 4) * 16;

    for (int i = 0; i < NC; i++) {
        if (i + 1 < NC) cp_wait<1>(); else cp_wait<0>();
        __syncthreads();

        uint32_t st = sb + (i % NSTAGE) * STG;
#pragma unroll
        for (int kh = 0; kh < 4; kh++) {
            uint32_t Af[4][4];
            uint32_t Bf[8][2];
#pragma unroll
            for (int mt = 0; mt < 4; mt++) {
                uint32_t addr = st + (wy * 64 + mt * 16 + arow) * ASTRIDE + kh * 32 + akof;
                ldmx4(Af[mt], addr);
            }
#pragma unroll
            for (int ntp = 0; ntp < 4; ntp++) {
                uint32_t addr = st + ATILE + (kh * 16 + vrow) * BSTRIDE +
                                (wx * 64 + ntp * 16) * 2 + vbyt;
                uint32_t r[4];
                ldmx4t(r, addr);
                Bf[ntp * 2][0] = r[0]; Bf[ntp * 2][1] = r[1];
                Bf[ntp * 2 + 1][0] = r[2]; Bf[ntp * 2 + 1][1] = r[3];
            }
#pragma unroll
            for (int mt = 0; mt < 4; mt++)
#pragma unroll
                for (int nt = 0; nt < 8; nt++)
                    mma16816(acc[mt][nt], Af[mt], Bf[nt]);
        }

        if (i + 2 < NC) {
            load_stage(A, Bp, m0, (i + 2) * BKC, K, bN, sb + ((i + 2) % NSTAGE) * STG);
            cp_commit();
        }
    }

    // Epilogue
#pragma unroll
    for (int mt = 0; mt < 4; mt++) {
#pragma unroll
        for (int nt = 0; nt < 8; nt++) {
            int r0 = m0 + wy * 64 + mt * 16 + (lane >> 2);
            int c  = n0 + wx * 64 + nt * 8 + (lane & 3) * 2;
            float b0 = bias[c], b1 = bias[c + 1];
#pragma unroll
            for (int half = 0; half < 2; half++) {
                int r = r0 + half * 8;
                float v0 = acc[mt][nt][half * 2 + 0] + b0;
                float v1 = acc[mt][nt][half * 2 + 1] + b1;
                size_t o = (size_t)r * N + c;
                if (mode >= 2) {
                    if (mode == 2) { v0 = fmaxf(v0, 0.f); v1 = fmaxf(v1, 0.f); }
                    *(uint32_t*)(outH + o) = pack2h(v0, v1);
                } else {
                    if (mode == 1) {
                        float2 rr = *(const float2*)(res + o);
                        v0 += rr.x; v1 += rr.y;
                    }
                    float2 w; w.x = v0; w.y = v1;
                    *(float2*)(outF + o) = w;
                }
            }
        }
    }
}

// ===========================================================================
// HMMA fp16 flash attention (causal), exp2-domain softmax, pre-scaled Q.
// Round-14 structure (2-stage, 2 barriers, interior fast path, NO gmax),
// reshaped: 64 q-rows per CTA, 4 warps / 128 threads, 4 CTAs/SM.
// ===========================================================================
#define AQ 64
#define ATK 64
#define ASTR 144
#define A_Q 0
#define A_ST (64 * ASTR)                      // 9216 (Q tile: 64 rows)
#define A_STG (2 * 64 * ASTR)                 // 18432 per stage (K + V)
#define A_V (64 * ASTR)
#define ATT_SMEM (A_ST + 2 * A_STG)           // 46080 (x4 CTAs = 180KB/SM)

__device__ __forceinline__ void load_kv_tile(
    const __half* __restrict__ kp, const __half* __restrict__ vp,
    size_t gbase, int k0, uint32_t sbase)
{
    int tid = threadIdx.x;
#pragma unroll
    for (int j = 0; j < 4; j++) {
        int e = tid + j * 128;
        int row = e >> 3, ch = e & 7;
        size_t g = gbase + (size_t)(k0 + row) * NQKV + ch * 8;
        uint32_t so = row * ASTR + ch * 16;
        cp_async16(sbase + so,       kp + g);
        cp_async16(sbase + A_V + so, vp + g);
    }
}

__global__ __launch_bounds__(128, 4) void flash_hmma_kernel(
    const __half* __restrict__ qkv, __half* __restrict__ O)
{
    extern __shared__ char smem[];
    uint32_t sb = smem_to_u32(smem);
    int tid = threadIdx.x, wid = tid >> 5, lane = tid & 31;
    int bh = blockIdx.y, b = bh >> 4, h = bh & 15;
    int q0 = (gridDim.x - 1 - blockIdx.x) * AQ;   // heavy tiles first
    size_t gbase = (size_t)(b * SEQ) * NQKV + h * DKH;

    const __half* qp = qkv;
    const __half* kp = qkv + DMODEL;
    const __half* vp = qkv + 2 * DMODEL;

    // Q tile: 64 rows x 8 chunks = 512 chunks / 128 threads
#pragma unroll
    for (int j = 0; j < 4; j++) {
        int e = tid + j * 128;
        int row = e >> 3, ch = e & 7;
        size_t g = gbase + (size_t)(q0 + row) * NQKV + ch * 8;
        cp_async16(sb + A_Q + row * ASTR + ch * 16, qp + g);
    }
    load_kv_tile(kp, vp, gbase, 0, sb + A_ST);
    cp_commit();

    const int ntiles = q0 / ATK + 1;

    float Sv[32], Oa[32];
#pragma unroll
    for (int i = 0; i < 32; i++) Oa[i] = 0.f;
    float m0 = -1e30f, m1 = -1e30f, l0 = 0.f, l1 = 0.f;

    int arow = (lane & 7) + ((lane >> 3) & 1) * 8;
    int akof = (lane >> 4) * 16;
    int brow = (lane & 7) + (lane >> 4) * 8;
    int bkof = ((lane >> 3) & 1) * 16;
    int vrow = (lane & 7) + ((lane >> 3) & 1) * 8;
    int vbyt = (lane >> 4) * 16;

    int wq = q0 + (wid << 4);
    int qrow0 = wq + (lane >> 2);

    for (int jt = 0; jt < ntiles; jt++) {
        int s = jt & 1;
        if (jt + 1 < ntiles) {
            load_kv_tile(kp, vp, gbase, (jt + 1) * ATK, sb + A_ST + (s ^ 1) * A_STG);
            cp_commit();
            cp_wait<1>();
        } else {
            cp_wait<0>();
        }
        __syncthreads();

        int k0 = jt * ATK;
        if (k0 <= wq + 15) {
            uint32_t stk = sb + A_ST + s * A_STG;
#pragma unroll
            for (int i = 0; i < 32; i++) Sv[i] = 0.f;
            // --- scores: Q x K^T (already scaled to log2 domain) ---
#pragma unroll
            for (int ks = 0; ks < 4; ks++) {
                uint32_t qf[4];
                uint32_t qaddr = sb + A_Q + (wid * 16 + arow) * ASTR + ks * 32 + akof;
                ldmx4(qf, qaddr);
#pragma unroll
                for (int g = 0; g < 4; g++) {
                    uint32_t kf[4];
                    uint32_t kaddr = stk + (g * 16 + brow) * ASTR + ks * 32 + bkof;
                    ldmx4(kf, kaddr);
                    mma16816(&Sv[(g * 2) * 4],     qf, &kf[0]);
                    mma16816(&Sv[(g * 2 + 1) * 4], qf, &kf[2]);
                }
            }
            // --- tile max (mask-free interior fast path vs diagonal mask) ---
            float mt0 = -1e30f, mt1 = -1e30f;
            if (k0 + ATK - 1 <= wq) {
#pragma unroll
                for (int j = 0; j < 8; j++) {
                    mt0 = fmaxf(mt0, fmaxf(Sv[j * 4 + 0], Sv[j * 4 + 1]));
                    mt1 = fmaxf(mt1, fmaxf(Sv[j * 4 + 2], Sv[j * 4 + 3]));
                }
            } else {
                int keyb = k0 + ((lane & 3) << 1);
#pragma unroll
                for (int j = 0; j < 8; j++) {
                    int key = keyb + j * 8;
                    float s0 = Sv[j * 4 + 0]; if (key     > qrow0)     s0 = -1e30f;
                    float s1 = Sv[j * 4 + 1]; if (key + 1 > qrow0)     s1 = -1e30f;
                    float s2 = Sv[j * 4 + 2]; if (key     > qrow0 + 8) s2 = -1e30f;
                    float s3 = Sv[j * 4 + 3]; if (key + 1 > qrow0 + 8) s3 = -1e30f;
                    Sv[j * 4 + 0] = s0; Sv[j * 4 + 1] = s1;
                    Sv[j * 4 + 2] = s2; Sv[j * 4 + 3] = s3;
                    mt0 = fmaxf(mt0, fmaxf(s0, s1));
                    mt1 = fmaxf(mt1, fmaxf(s2, s3));
                }
            }
            mt0 = fmaxf(mt0, __shfl_xor_sync(0xffffffffu, mt0, 1));
            mt0 = fmaxf(mt0, __shfl_xor_sync(0xffffffffu, mt0, 2));
            mt1 = fmaxf(mt1, __shfl_xor_sync(0xffffffffu, mt1, 1));
            mt1 = fmaxf(mt1, __shfl_xor_sync(0xffffffffu, mt1, 2));
            float mn0 = fmaxf(m0, mt0), mn1 = fmaxf(m1, mt1);
            float c0 = exp2f(m0 - mn0), c1 = exp2f(m1 - mn1);
            l0 *= c0; l1 *= c1;
#pragma unroll
            for (int j = 0; j < 8; j++) {
                Oa[j * 4 + 0] *= c0; Oa[j * 4 + 1] *= c0;
                Oa[j * 4 + 2] *= c1; Oa[j * 4 + 3] *= c1;
            }
            float sum0 = 0.f, sum1 = 0.f;
#pragma unroll
            for (int j = 0; j < 8; j++) {
                float p0 = exp2f(Sv[j * 4 + 0] - mn0);
                float p1 = exp2f(Sv[j * 4 + 1] - mn0);
                float p2 = exp2f(Sv[j * 4 + 2] - mn1);
                float p3 = exp2f(Sv[j * 4 + 3] - mn1);
                Sv[j * 4 + 0] = p0; Sv[j * 4 + 1] = p1;
                Sv[j * 4 + 2] = p2; Sv[j * 4 + 3] = p3;
                sum0 += p0 + p1; sum1 += p2 + p3;
            }
            sum0 += __shfl_xor_sync(0xffffffffu, sum0, 1);
            sum0 += __shfl_xor_sync(0xffffffffu, sum0, 2);
            sum1 += __shfl_xor_sync(0xffffffffu, sum1, 1);
            sum1 += __shfl_xor_sync(0xffffffffu, sum1, 2);
            l0 += sum0; l1 += sum1;
            m0 = mn0; m1 = mn1;
            // --- P x V ---
#pragma unroll
            for (int ks = 0; ks < 4; ks++) {
                uint32_t pf[4];
                pf[0] = pack2h(Sv[8 * ks + 0], Sv[8 * ks + 1]);
                pf[1] = pack2h(Sv[8 * ks + 2], Sv[8 * ks + 3]);
                pf[2] = pack2h(Sv[8 * ks + 4], Sv[8 * ks + 5]);
                pf[3] = pack2h(Sv[8 * ks + 6], Sv[8 * ks + 7]);
#pragma unroll
                for (int nt = 0; nt < 4; nt++) {
                    uint32_t vf[4];
                    uint32_t vaddr = stk + A_V + (ks * 16 + vrow) * ASTR + nt * 32 + vbyt;
                    ldmx4t(vf, vaddr);
                    mma16816(&Oa[(nt * 2) * 4],     pf, &vf[0]);
                    mma16816(&Oa[(nt * 2 + 1) * 4], pf, &vf[2]);
                }
            }
        }
        __syncthreads();
    }

    float inv0 = 1.f / l0, inv1 = 1.f / l1;
    size_t obase = (size_t)(b * SEQ) * DMODEL + h * DKH;
    size_t r0 = obase + (size_t)qrow0 * DMODEL;
    size_t r1 = obase + (size_t)(qrow0 + 8) * DMODEL;
#pragma unroll
    for (int nt = 0; nt < 8; nt++) {
        int col = nt * 8 + (lane & 3) * 2;
        *(uint32_t*)(O + r0 + col) = pack2h(Oa[nt * 4 + 0] * inv0, Oa[nt * 4 + 1] * inv0);
        *(uint32_t*)(O + r1 + col) = pack2h(Oa[nt * 4 + 2] * inv1, Oa[nt * 4 + 3] * inv1);
    }
}

// ===========================================================================
// Launcher
// ===========================================================================
extern "C" void kernel_launch(void* const* d_in, const int* in_sizes, int n_in,
                              void* d_out, int out_size)
{
    const float* x   = (const float*)d_in[0];
    const float* Wq  = (const float*)d_in[2];
    const float* bq  = (const float*)d_in[3];
    const float* Wk  = (const float*)d_in[4];
    const float* bk  = (const float*)d_in[5];
    const float* Wv  = (const float*)d_in[6];
    const float* bv  = (const float*)d_in[7];
    const float* Wo  = (const float*)d_in[8];
    const float* bo  = (const float*)d_in[9];
    const float* W1  = (const float*)d_in[10];
    const float* b1  = (const float*)d_in[11];
    const float* W2  = (const float*)d_in[12];
    const float* b2  = (const float*)d_in[13];
    const float* g1  = (const float*)d_in[14];
    const float* be1 = (const float*)d_in[15];
    const float* g2  = (const float*)d_in[16];
    const float* be2 = (const float*)d_in[17];
    float* out = (float*)d_out;

    __half *xn, *at, *ff, *qkv, *w;
    float *h, *bqkv;
    cudaGetSymbolAddress((void**)&xn, g_xn);
    cudaGetSymbolAddress((void**)&at, g_at);
    cudaGetSymbolAddress((void**)&ff, g_ff);
    cudaGetSymbolAddress((void**)&qkv, g_qkv);
    cudaGetSymbolAddress((void**)&w, g_w);
    cudaGetSymbolAddress((void**)&h, g_h);
    cudaGetSymbolAddress((void**)&bqkv, g_bqkv);

    cudaFuncSetAttribute(gemm_hmma_kernel,
                         cudaFuncAttributeMaxDynamicSharedMemorySize, GSMEM);
    cudaFuncSetAttribute(flash_hmma_kernel,
                         cudaFuncAttributeMaxDynamicSharedMemorySize, ATT_SMEM);

    // 1. prep: weight fp32->fp16 convert (Wq/bq pre-scaled) + bias concat
    prep_kernel<<<6144, 256>>>(Wq, Wk, Wv, Wo, W1, W2, bq, bk, bv, w, bqkv);
    // 2. LN1 -> fp16
    ln_kernel<<<NROWS, 256>>>(x, g1, be1, xn);
    // 3. Fused QKV projection -> fp16 (mode 3), 768 CTAs
    dim3 gQKV(NQKV / 128, NROWS / 128);
    gemm_hmma_kernel<<<gQKV, 128, GSMEM>>>(xn, w, bqkv, nullptr, nullptr, qkv,
                                           NQKV, DMODEL, 1024, 1 << 20, 1024, 3);
    // 4. Causal flash attention -> fp16 (1024 CTAs, 4 warps each)
    dim3 gA(SEQ / AQ, BATCH * NHEAD);
    flash_hmma_kernel<<<gA, 128, ATT_SMEM>>>(qkv, at);
    // 5. Output projection + residual(x) -> h (fp32), 256 CTAs
    dim3 gO(DMODEL / 128, NROWS / 128);
    gemm_hmma_kernel<<<gO, 128, GSMEM>>>(at, w + WOFF_O, bo, x, h, nullptr,
                                         DMODEL, DMODEL, DMODEL, 0, DMODEL, 1);
    // 6. LN2 -> fp16
    ln_kernel<<<NROWS, 256>>>(h, g2, be2, xn);
    // 7. FFN1 + relu -> fp16, 1024 CTAs
    dim3 gF1(DFF / 128, NROWS / 128);
    gemm_hmma_kernel<<<gF1, 128, GSMEM>>>(xn, w + WOFF_W1, b1, nullptr, nullptr, ff,
                                          DFF, DMODEL, DFF, 0, DFF, 2);
    // 8. FFN2 + residual(h) -> out (fp32), 256 CTAs
    dim3 gF2(DMODEL / 128, NROWS / 128);
    gemm_hmma_kernel<<<gF2, 128, GSMEM>>>(ff, w + WOFF_W2, b2, h, out, nullptr,
                                          DMODEL, DFF, DMODEL, 0, DMODEL, 1);
}